// round 15
// baseline (speedup 1.0000x reference)
#include <cuda_runtime.h>
#include <cuda.h>
#include <cstdint>

#define NS       8192
#define NC       1024
#define NK       4
#define TILE     32            // channels per block tile
#define THREADS  128           // samples per block (1 per thread)
#define PAD      4
#define WROW     40            // words per comp window row
#define CSTRIDE  168           // copy stride; 168 % 32 == 8 -> disjoint 8-bank groups

__global__ void __launch_bounds__(THREADS)
smf_kernel(const float* __restrict__ comp,      // [4, 1024]
           const float* __restrict__ contrib,   // [8192, 4]
           const float* __restrict__ shift,     // [8192, 4]
           const __grid_constant__ CUtensorMap tmap)   // out [8192, 1024] f32, SW128
{
    __shared__ __align__(16)   float sc[3 * CSTRIDE + NK * WROW + 8]; // 4 shifted copies
    __shared__ __align__(1024) float st[THREADS * TILE];              // 16KB SW128 tile

    const int tid  = threadIdx.x;
    const int tile = blockIdx.x & 31;           // 32 channel tiles
    const int grp  = blockIdx.x >> 5;           // 64 sample groups
    const int c0   = tile * TILE;
    const int s0   = grp * THREADS;

    // prefetch per-sample params (hide LDG latency under window fill)
    const float4 sh4 = __ldg((const float4*)(shift   + (size_t)(s0 + tid) * NK));
    const float4 cn4 = __ldg((const float4*)(contrib + (size_t)(s0 + tid) * NK));

    // ---- fill 4 copies: copy c, row k, word w = comp[k, c0-4+c+w] (OOB=0) ----
    #pragma unroll
    for (int t = tid; t < 4 * NK * WROW; t += THREADS) {   // 5 iterations
        const int cpy = t / (NK * WROW);
        const int rem = t - cpy * (NK * WROW);
        const int k = rem / WROW, w = rem - k * WROW;
        const int j = c0 - PAD + cpy + w;
        sc[cpy * CSTRIDE + k * WROW + w] = (j >= 0 && j < NC) ? comp[k * NC + j] : 0.0f;
    }

    const float shv[NK] = { sh4.x, sh4.y, sh4.z, sh4.w };
    const float cnv[NK] = { cn4.x, cn4.y, cn4.z, cn4.w };

    float a[NK], b[NK];
    const float4* base[NK];                     // register smem base -> LDS [R+imm]
    #pragma unroll
    for (int k = 0; k < NK; k++) {
        const float sh = shv[k];
        const float cn = cnv[k];
        int   fi = (int)floorf(sh);             // in [-4, 4]
        float fr = sh - (float)fi;
        if (fi > 3)  { fr += (float)(fi - 3); fi = 3; }   // shift==4.0 edge
        if (fi < -4) { fi = -4; }
        b[k] = cn * fr;                         // weight of tap fi+1
        a[k] = cn - b[k];                       // cn*(1-fr)
        const int c = fi & 3;                   // copy index (0..3, incl. negative fi)
        base[k] = (const float4*)&sc[c * CSTRIDE + k * WROW + (fi + 4 - c)]; // 4-aligned
    }
    __syncthreads();

    // ---- main: per 4 channels per k: 1 LDS.128 (1 wavefront) + 8 FFMA ----
    float4 u[NK];
    #pragma unroll
    for (int k = 0; k < NK; k++) u[k] = base[k][0];

    float4* st4 = (float4*)st;
    const int xorl = tid & 7;                   // SW128 column xor for this row
    #pragma unroll
    for (int q = 0; q < TILE / 4; q++) {        // channels 4q .. 4q+3
        // split accumulators: g[0] for k=0,1 / g[1] for k=2,3 (halves chain depth)
        float g0[2] = {0.f, 0.f}, g1[2] = {0.f, 0.f};
        float g2[2] = {0.f, 0.f}, g3[2] = {0.f, 0.f};
        #pragma unroll
        for (int k = 0; k < NK; k++) {
            const int h = k >> 1;               // compile-time constant after unroll
            const float4 v = base[k][q + 1];
            g0[h] += a[k] * u[k].x + b[k] * u[k].y;
            g1[h] += a[k] * u[k].y + b[k] * u[k].z;
            g2[h] += a[k] * u[k].z + b[k] * u[k].w;
            g3[h] += a[k] * u[k].w + b[k] * v.x;
            u[k] = v;
        }
        st4[tid * 8 + (q ^ xorl)] =             // SW128-swizzled STS.128, conflict-free
            make_float4(g0[0] + g0[1], g1[0] + g1[1], g2[0] + g2[1], g3[0] + g3[1]);
    }

    // ---- one TMA tensor store for the whole [128 x 32] tile ----
    asm volatile("fence.proxy.async.shared::cta;" ::: "memory");
    __syncthreads();
    if (tid == 0) {
        const uint32_t st_u32 = (uint32_t)__cvta_generic_to_shared(st);
        asm volatile(
            "cp.async.bulk.tensor.2d.global.shared::cta.tile.bulk_group "
            "[%0, {%1, %2}], [%3];"
            :: "l"(&tmap), "r"(c0), "r"(s0), "r"(st_u32)
            : "memory");
        asm volatile("cp.async.bulk.commit_group;" ::: "memory");
        asm volatile("cp.async.bulk.wait_group 0;" ::: "memory");
    }
}

// ---- host: tensormap via runtime driver-entry-point (no -lcuda link) ----
typedef CUresult (*PFN_encodeTiled)(
    CUtensorMap*, CUtensorMapDataType, cuuint32_t, void*,
    const cuuint64_t*, const cuuint64_t*, const cuuint32_t*, const cuuint32_t*,
    CUtensorMapInterleave, CUtensorMapSwizzle, CUtensorMapL2promotion,
    CUtensorMapFloatOOBfill);

static PFN_encodeTiled get_encoder()
{
    static PFN_encodeTiled fn = nullptr;
    if (!fn) {
        void* p = nullptr;
        cudaDriverEntryPointQueryResult qr;
#if CUDART_VERSION >= 12050
        cudaGetDriverEntryPointByVersion("cuTensorMapEncodeTiled", &p, 12000,
                                         cudaEnableDefault, &qr);
#else
        cudaGetDriverEntryPoint("cuTensorMapEncodeTiled", &p,
                                cudaEnableDefault, &qr);
#endif
        fn = (PFN_encodeTiled)p;
    }
    return fn;
}

extern "C" void kernel_launch(void* const* d_in, const int* in_sizes, int n_in,
                              void* d_out, int out_size)
{
    // inputs [8192,1024] (ignored), components [4,1024],
    // contributions [8192,4], shift [8192,4]
    const float* comp    = (const float*)d_in[1];
    const float* contrib = (const float*)d_in[2];
    const float* shift   = (const float*)d_in[3];

    CUtensorMap tmap;
    {
        cuuint64_t dims[2]    = { NC, NS };           // inner = channels
        cuuint64_t strides[1] = { NC * sizeof(float) };
        cuuint32_t box[2]     = { TILE, THREADS };    // 32 ch x 128 samples
        cuuint32_t estr[2]    = { 1, 1 };
        get_encoder()(&tmap, CU_TENSOR_MAP_DATA_TYPE_FLOAT32, 2, d_out,
                      dims, strides, box, estr,
                      CU_TENSOR_MAP_INTERLEAVE_NONE, CU_TENSOR_MAP_SWIZZLE_128B,
                      CU_TENSOR_MAP_L2_PROMOTION_L2_128B,
                      CU_TENSOR_MAP_FLOAT_OOB_FILL_NONE);
    }

    smf_kernel<<<32 * (NS / THREADS), THREADS>>>(comp, contrib, shift, tmap);  // 2048
}